// round 9
// baseline (speedup 1.0000x reference)
#include <cuda_runtime.h>
#include <cstdint>
#include <math_constants.h>

#define LOG2E 1.4426950408889634f

typedef unsigned long long u64;

// Scratch: 32 m-chunks x (8*4096) n's: locally-shifted partial sums + local max.
__device__ float g_partE[32 * 32768];
__device__ float g_partT[32 * 32768];
__device__ float g_partM[32 * 32768];
__device__ float g_blocksum[128];

__device__ __forceinline__ u64 f2fma(u64 a, u64 b, u64 c) {
    u64 r; asm("fma.rn.f32x2 %0,%1,%2,%3;" : "=l"(r) : "l"(a), "l"(b), "l"(c)); return r;
}
__device__ __forceinline__ u64 f2add(u64 a, u64 b) {
    u64 r; asm("add.rn.f32x2 %0,%1,%2;" : "=l"(r) : "l"(a), "l"(b)); return r;
}
__device__ __forceinline__ u64 f2mul(u64 a, u64 b) {
    u64 r; asm("mul.rn.f32x2 %0,%1,%2;" : "=l"(r) : "l"(a), "l"(b)); return r;
}
__device__ __forceinline__ u64 pk(float lo, float hi) {
    u64 r; asm("mov.b64 %0,{%1,%2};" : "=l"(r) : "f"(lo), "f"(hi)); return r;
}
__device__ __forceinline__ void up(u64 v, float& lo, float& hi) {
    asm("mov.b64 {%0,%1},%2;" : "=f"(lo), "=f"(hi) : "l"(v));
}
__device__ __forceinline__ float ex2f(float x) {
    float r; asm("ex2.approx.f32 %0,%1;" : "=f"(r) : "f"(x)); return r;
}

// B=8, N=4096, M=4096, D=3 hardcoded.
// Grid: 2048 blocks = 8 batches x 8 n-chunks x 32 m-chunks.
// Block: 256 threads; each thread owns 2 n's; block owns 128 m's.
// Online softmax: single pass over m, running max + rescaled accumulators.
__global__ void __launch_bounds__(256, 5) fape_fused_kernel(
    const float* __restrict__ Xp,   // (8,4096,3)
    const float* __restrict__ Xt,   // (8,4096,3)
    const float* __restrict__ Rp,   // (8,3,3)
    const float* __restrict__ tp,   // (8,3)
    const float* __restrict__ Rt,   // (8,3,3)
    const float* __restrict__ tt,   // (8,3)
    const float* __restrict__ temp) // (1,)
{
    // 64 m-pair groups x 4 packed u64: [vx01, vy01, vz01, vw01].
    __shared__ __align__(16) u64 sm[64 * 4];   // 2 KB

    const int mchunk = blockIdx.x & 31;
    const int nchunk = (blockIdx.x >> 5) & 7;
    const int b      = blockIdx.x >> 8;
    const int tid    = threadIdx.x;

    const float T = *temp;
    const float s = -LOG2E / T;   // logit scale in log2 domain (s < 0)

    // ---- Fill smem: v = (s*-2*Xt', s*|Xt'|^2) for this block's 128 m's ----
    if (tid < 128) {
        const float* R  = Rt + b * 9;
        const float* tv = tt + b * 3;
        const float r00 = R[0], r01 = R[1], r02 = R[2];
        const float r10 = R[3], r11 = R[4], r12 = R[5];
        const float r20 = R[6], r21 = R[7], r22 = R[8];
        const float tx = tv[0], ty = tv[1], tz = tv[2];
        const float s2 = s * -2.0f;

        const float* xm = Xt + (size_t)(b * 4096 + mchunk * 128 + tid) * 3;
        const float x = xm[0], y = xm[1], z = xm[2];
        const float ax = r00 * x + r01 * y + r02 * z + tx;
        const float ay = r10 * x + r11 * y + r12 * z + ty;
        const float az = r20 * x + r21 * y + r22 * z + tz;
        const float sq = ax * ax + ay * ay + az * az;
        const int j = tid >> 1, h = tid & 1;
        float* w = (float*)(sm + j * 4);
        w[0 + h] = s2 * ax;   // vx
        w[2 + h] = s2 * ay;   // vy
        w[4 + h] = s2 * az;   // vz
        w[6 + h] = s * sq;    // vw
    }

    // ---- Per-thread: two n's ----
    const float* Rq = Rp + b * 9;
    const float* tq = tp + b * 3;
    const float q00 = Rq[0], q01 = Rq[1], q02 = Rq[2];
    const float q10 = Rq[3], q11 = Rq[4], q12 = Rq[5];
    const float q20 = Rq[6], q21 = Rq[7], q22 = Rq[8];
    const float u0 = tq[0], u1 = tq[1], u2 = tq[2];

    const int n0 = nchunk * 512 + tid;      // and n1 = n0 + 256
    const float* xa = Xp + (size_t)(b * 4096 + n0) * 3;
    const float* xb = xa + 256 * 3;

    const float ax0 = xa[0], ay0 = xa[1], az0 = xa[2];
    const float px0 = q00 * ax0 + q01 * ay0 + q02 * az0 + u0;
    const float py0 = q10 * ax0 + q11 * ay0 + q12 * az0 + u1;
    const float pz0 = q20 * ax0 + q21 * ay0 + q22 * az0 + u2;
    const float sc0 = s * (px0 * px0 + py0 * py0 + pz0 * pz0);

    const float ax1 = xb[0], ay1 = xb[1], az1 = xb[2];
    const float px1 = q00 * ax1 + q01 * ay1 + q02 * az1 + u0;
    const float py1 = q10 * ax1 + q11 * ay1 + q12 * az1 + u1;
    const float pz1 = q20 * ax1 + q21 * ay1 + q22 * az1 + u2;
    const float sc1 = s * (px1 * px1 + py1 * py1 + pz1 * pz1);

    const u64 Px0 = pk(px0, px0), Py0 = pk(py0, py0), Pz0 = pk(pz0, pz0);
    const u64 Px1 = pk(px1, px1), Py1 = pk(py1, py1), Pz1 = pk(pz1, pz1);

    // Online-softmax state per n: running max M, scaled sums Se = Σe, Sg = Σe*(g-M).
    float M0 = -1e30f, M1 = -1e30f;
    u64 Se0 = 0ull, Sg0 = 0ull, Se1 = 0ull, Sg1 = 0ull;

    __syncthreads();

    // 16 tiles x (4 groups = 8 m's).
    #pragma unroll 2
    for (int t = 0; t < 16; t++) {
        const u64* base = sm + t * 16;

        // Raw logits (minus sc): g = vw + p.v, packed 2 m's per reg.
        u64 g0[4], g1[4];
        #pragma unroll
        for (int k = 0; k < 4; k++) {
            const ulonglong2 v1 = *(const ulonglong2*)(base + k * 4);     // vx, vy
            const ulonglong2 v2 = *(const ulonglong2*)(base + k * 4 + 2); // vz, vw
            u64 a = f2fma(Pz0, v2.x, v2.y);
            a = f2fma(Py0, v1.y, a);
            g0[k] = f2fma(Px0, v1.x, a);
            u64 c = f2fma(Pz1, v2.x, v2.y);
            c = f2fma(Py1, v1.y, c);
            g1[k] = f2fma(Px1, v1.x, c);
        }

        // Tile maxes (scalar FMNMX tree on the ALU pipe).
        float lo, hi, tm0, tm1;
        up(g0[0], lo, hi); tm0 = fmaxf(lo, hi);
        up(g0[1], lo, hi); tm0 = fmaxf(tm0, fmaxf(lo, hi));
        up(g0[2], lo, hi); tm0 = fmaxf(tm0, fmaxf(lo, hi));
        up(g0[3], lo, hi); tm0 = fmaxf(tm0, fmaxf(lo, hi));
        up(g1[0], lo, hi); tm1 = fmaxf(lo, hi);
        up(g1[1], lo, hi); tm1 = fmaxf(tm1, fmaxf(lo, hi));
        up(g1[2], lo, hi); tm1 = fmaxf(tm1, fmaxf(lo, hi));
        up(g1[3], lo, hi); tm1 = fmaxf(tm1, fmaxf(lo, hi));

        // Running max update + branchless rescale.
        const float Mn0 = fmaxf(M0, tm0);
        const float Mn1 = fmaxf(M1, tm1);
        const float d0s = M0 - Mn0;             // <= 0
        const float d1s = M1 - Mn1;
        const float w0 = ex2f(d0s);
        const float w1 = ex2f(d1s);
        const u64 D0 = pk(d0s, d0s), W0 = pk(w0, w0);
        const u64 D1 = pk(d1s, d1s), W1 = pk(w1, w1);
        // Sg = (Sg + dM*Se) * w ; Se = Se * w
        Sg0 = f2mul(f2fma(D0, Se0, Sg0), W0);
        Se0 = f2mul(Se0, W0);
        Sg1 = f2mul(f2fma(D1, Se1, Sg1), W1);
        Se1 = f2mul(Se1, W1);
        M0 = Mn0;
        M1 = Mn1;

        const u64 NM0 = pk(-Mn0, -Mn0);
        const u64 NM1 = pk(-Mn1, -Mn1);

        #pragma unroll
        for (int k = 0; k < 4; k++) {
            const u64 dd0 = f2add(g0[k], NM0);   // shifted logit <= 0
            const u64 dd1 = f2add(g1[k], NM1);
            float a0, c0, a1, c1;
            up(dd0, a0, c0);
            up(dd1, a1, c1);
            const u64 E0 = pk(ex2f(a0), ex2f(c0));
            const u64 E1 = pk(ex2f(a1), ex2f(c1));
            Se0 = f2add(Se0, E0);
            Sg0 = f2fma(E0, dd0, Sg0);
            Se1 = f2add(Se1, E1);
            Sg1 = f2fma(E1, dd1, Sg1);
        }
    }

    // Write partials: (E_c, T_c, M_c) per (n, mchunk). Logit max M_c = sc + M.
    float e0, e1, t0, t1;
    const int gbase = mchunk * 32768 + b * 4096 + nchunk * 512 + tid;
    up(Se0, e0, e1); up(Sg0, t0, t1);
    g_partE[gbase] = e0 + e1;
    g_partT[gbase] = t0 + t1;
    g_partM[gbase] = sc0 + M0;
    up(Se1, e0, e1); up(Sg1, t0, t1);
    g_partE[gbase + 256] = e0 + e1;
    g_partT[gbase + 256] = t0 + t1;
    g_partM[gbase + 256] = sc1 + M1;
}

// Exact combine of locally-shifted partials per n; per-block partial sums.
__global__ void __launch_bounds__(256) fape_reduce_kernel(
    const float* __restrict__ temp)
{
    const int idx = blockIdx.x * 256 + threadIdx.x;   // 0..32767
    float M = -CUDART_INF_F;
    #pragma unroll
    for (int c = 0; c < 32; c++)
        M = fmaxf(M, g_partM[c * 32768 + idx]);

    float E = 0.0f, Tg = 0.0f;
    #pragma unroll
    for (int c = 0; c < 32; c++) {
        const float dm = g_partM[c * 32768 + idx] - M;   // <= 0
        const float w  = ex2f(dm);
        const float Ec = g_partE[c * 32768 + idx];
        const float Tc = g_partT[c * 32768 + idx];
        E  = fmaf(w, Ec, E);
        Tg = fmaf(w, fmaf(dm, Ec, Tc), Tg);  // w*(Tc + dm*Ec)
    }
    const float invs = -(*temp) / LOG2E;     // 1/s
    // E >= 1 (the argmax chunk contributes its max term = 1).
    const float weighted = invs * (Tg / E + M);

    __shared__ float red[256];
    red[threadIdx.x] = weighted;
    __syncthreads();
    #pragma unroll
    for (int off = 128; off > 0; off >>= 1) {
        if (threadIdx.x < off) red[threadIdx.x] += red[threadIdx.x + off];
        __syncthreads();
    }
    if (threadIdx.x == 0)
        g_blocksum[blockIdx.x] = red[0];
}

// Final: sum 128 block partials, write the mean.
__global__ void fape_final_kernel(float* __restrict__ out) {
    const int tid = threadIdx.x;   // 128 threads
    float v = g_blocksum[tid];
    #pragma unroll
    for (int off = 16; off > 0; off >>= 1)
        v += __shfl_xor_sync(0xffffffffu, v, off);
    __shared__ float warp_s[4];
    if ((tid & 31) == 0) warp_s[tid >> 5] = v;
    __syncthreads();
    if (tid == 0)
        *out = (warp_s[0] + warp_s[1] + warp_s[2] + warp_s[3]) * (1.0f / (8.0f * 4096.0f));
}

extern "C" void kernel_launch(void* const* d_in, const int* in_sizes, int n_in,
                              void* d_out, int out_size) {
    const float* Xp   = (const float*)d_in[0];
    const float* Xt   = (const float*)d_in[1];
    const float* Rp   = (const float*)d_in[2];
    const float* tp   = (const float*)d_in[3];
    const float* Rt   = (const float*)d_in[4];
    const float* tt   = (const float*)d_in[5];
    const float* temp = (const float*)d_in[6];
    float* out = (float*)d_out;

    fape_fused_kernel<<<2048, 256>>>(Xp, Xt, Rp, tp, Rt, tt, temp);
    fape_reduce_kernel<<<128, 256>>>(temp);
    fape_final_kernel<<<1, 128>>>(out);
}

// round 11
// speedup vs baseline: 1.0199x; 1.0199x over previous
#include <cuda_runtime.h>
#include <cstdint>
#include <math_constants.h>

#define LOG2E 1.4426950408889634f

typedef unsigned long long u64;

// Scratch: 32 m-chunks x (8*4096) n's: locally-shifted partial sums + local max.
__device__ float g_partE[32 * 32768];
__device__ float g_partT[32 * 32768];
__device__ float g_partM[32 * 32768];
__device__ float g_blocksum[128];

__device__ __forceinline__ u64 f2fma(u64 a, u64 b, u64 c) {
    u64 r; asm("fma.rn.f32x2 %0,%1,%2,%3;" : "=l"(r) : "l"(a), "l"(b), "l"(c)); return r;
}
__device__ __forceinline__ u64 f2add(u64 a, u64 b) {
    u64 r; asm("add.rn.f32x2 %0,%1,%2;" : "=l"(r) : "l"(a), "l"(b)); return r;
}
__device__ __forceinline__ u64 f2mul(u64 a, u64 b) {
    u64 r; asm("mul.rn.f32x2 %0,%1,%2;" : "=l"(r) : "l"(a), "l"(b)); return r;
}
__device__ __forceinline__ u64 pk(float lo, float hi) {
    u64 r; asm("mov.b64 %0,{%1,%2};" : "=l"(r) : "f"(lo), "f"(hi)); return r;
}
__device__ __forceinline__ void up(u64 v, float& lo, float& hi) {
    asm("mov.b64 {%0,%1},%2;" : "=f"(lo), "=f"(hi) : "l"(v));
}
__device__ __forceinline__ float ex2f(float x) {
    float r; asm("ex2.approx.f32 %0,%1;" : "=f"(r) : "f"(x)); return r;
}

// B=8, N=4096, M=4096, D=3 hardcoded.
// Grid: 2048 blocks = 8 batches x 8 n-chunks x 32 m-chunks.
// Block: 256 threads; each thread owns 2 n's; block owns 128 m's.
// Online softmax, 16-m tiles, scalar max tree; n0/n1 processed sequentially
// per tile to keep one g[8] array live (register pressure).
__global__ void __launch_bounds__(256, 4) fape_fused_kernel(
    const float* __restrict__ Xp,   // (8,4096,3)
    const float* __restrict__ Xt,   // (8,4096,3)
    const float* __restrict__ Rp,   // (8,3,3)
    const float* __restrict__ tp,   // (8,3)
    const float* __restrict__ Rt,   // (8,3,3)
    const float* __restrict__ tt,   // (8,3)
    const float* __restrict__ temp) // (1,)
{
    // 64 m-pair groups x 4 packed u64: [vx01, vy01, vz01, vw01].
    __shared__ __align__(16) u64 sm[64 * 4];   // 2 KB

    const int mchunk = blockIdx.x & 31;
    const int nchunk = (blockIdx.x >> 5) & 7;
    const int b      = blockIdx.x >> 8;
    const int tid    = threadIdx.x;

    const float T = *temp;
    const float s = -LOG2E / T;   // logit scale in log2 domain (s < 0)

    // ---- Fill smem: v = (s*-2*Xt', s*|Xt'|^2) for this block's 128 m's ----
    if (tid < 128) {
        const float* R  = Rt + b * 9;
        const float* tv = tt + b * 3;
        const float r00 = R[0], r01 = R[1], r02 = R[2];
        const float r10 = R[3], r11 = R[4], r12 = R[5];
        const float r20 = R[6], r21 = R[7], r22 = R[8];
        const float tx = tv[0], ty = tv[1], tz = tv[2];
        const float s2 = s * -2.0f;

        const float* xm = Xt + (size_t)(b * 4096 + mchunk * 128 + tid) * 3;
        const float x = xm[0], y = xm[1], z = xm[2];
        const float ax = r00 * x + r01 * y + r02 * z + tx;
        const float ay = r10 * x + r11 * y + r12 * z + ty;
        const float az = r20 * x + r21 * y + r22 * z + tz;
        const float sq = ax * ax + ay * ay + az * az;
        const int j = tid >> 1, h = tid & 1;
        float* w = (float*)(sm + j * 4);
        w[0 + h] = s2 * ax;   // vx
        w[2 + h] = s2 * ay;   // vy
        w[4 + h] = s2 * az;   // vz
        w[6 + h] = s * sq;    // vw
    }

    // ---- Per-thread: two n's ----
    const float* Rq = Rp + b * 9;
    const float* tq = tp + b * 3;
    const float q00 = Rq[0], q01 = Rq[1], q02 = Rq[2];
    const float q10 = Rq[3], q11 = Rq[4], q12 = Rq[5];
    const float q20 = Rq[6], q21 = Rq[7], q22 = Rq[8];
    const float u0 = tq[0], u1 = tq[1], u2 = tq[2];

    const int n0 = nchunk * 512 + tid;      // and n1 = n0 + 256
    u64 PX[2], PY[2], PZ[2];
    float SC[2];
    #pragma unroll
    for (int nn = 0; nn < 2; nn++) {
        const float* xa = Xp + (size_t)(b * 4096 + n0 + nn * 256) * 3;
        const float ax = xa[0], ay = xa[1], az = xa[2];
        const float px = q00 * ax + q01 * ay + q02 * az + u0;
        const float py = q10 * ax + q11 * ay + q12 * az + u1;
        const float pz = q20 * ax + q21 * ay + q22 * az + u2;
        SC[nn] = s * (px * px + py * py + pz * pz);
        PX[nn] = pk(px, px);
        PY[nn] = pk(py, py);
        PZ[nn] = pk(pz, pz);
    }

    // Online-softmax state per n: running max M, scaled sums Se = Σe, Sg = Σe*(g-M).
    float Mx[2] = { -1e30f, -1e30f };
    u64 SE[2] = { 0ull, 0ull };
    u64 SG[2] = { 0ull, 0ull };

    __syncthreads();

    // 8 tiles x (8 groups = 16 m's); n0 and n1 sequential within a tile.
    for (int t = 0; t < 8; t++) {
        const u64* base = sm + t * 32;

        #pragma unroll
        for (int nn = 0; nn < 2; nn++) {
            const u64 px = PX[nn], py = PY[nn], pz = PZ[nn];

            // Raw logits (minus sc): g = vw + p.v, packed 2 m's per reg.
            u64 g[8];
            #pragma unroll
            for (int k = 0; k < 8; k++) {
                const ulonglong2 v1 = *(const ulonglong2*)(base + k * 4);     // vx, vy
                const ulonglong2 v2 = *(const ulonglong2*)(base + k * 4 + 2); // vz, vw
                u64 a = f2fma(pz, v2.x, v2.y);
                a = f2fma(py, v1.y, a);
                g[k] = f2fma(px, v1.x, a);
            }

            // Scalar max tree over the 16 logits (ALU pipe; unpack is reg aliasing).
            float m8[8];
            #pragma unroll
            for (int k = 0; k < 8; k++) {
                float lo, hi;
                up(g[k], lo, hi);
                m8[k] = fmaxf(lo, hi);
            }
            const float m04 = fmaxf(fmaxf(m8[0], m8[1]), fmaxf(m8[2], m8[3]));
            const float m48 = fmaxf(fmaxf(m8[4], m8[5]), fmaxf(m8[6], m8[7]));
            const float tm = fmaxf(m04, m48);

            // Running max update + branchless rescale (once per 16 m's).
            const float Mn = fmaxf(Mx[nn], tm);
            const float ds = Mx[nn] - Mn;        // <= 0
            const float w  = ex2f(ds);
            const u64 D = pk(ds, ds), W = pk(w, w);
            SG[nn] = f2mul(f2fma(D, SE[nn], SG[nn]), W);  // (Sg + dM*Se) * w
            SE[nn] = f2mul(SE[nn], W);
            Mx[nn] = Mn;

            const u64 NM = pk(-Mn, -Mn);
            u64 se = SE[nn], sg = SG[nn];
            #pragma unroll
            for (int k = 0; k < 8; k++) {
                const u64 dd = f2add(g[k], NM);   // shifted logit <= 0
                float a0, c0;
                up(dd, a0, c0);
                const u64 E = pk(ex2f(a0), ex2f(c0));
                se = f2add(se, E);
                sg = f2fma(E, dd, sg);
            }
            SE[nn] = se;
            SG[nn] = sg;
        }
    }

    // Write partials: (E_c, T_c, M_c) per (n, mchunk). Logit max M_c = sc + M.
    #pragma unroll
    for (int nn = 0; nn < 2; nn++) {
        float e0, e1, t0, t1;
        up(SE[nn], e0, e1);
        up(SG[nn], t0, t1);
        const int g = mchunk * 32768 + b * 4096 + nchunk * 512 + tid + nn * 256;
        g_partE[g] = e0 + e1;
        g_partT[g] = t0 + t1;
        g_partM[g] = SC[nn] + Mx[nn];
    }
}

// Exact combine of locally-shifted partials per n; per-block partial sums.
__global__ void __launch_bounds__(256) fape_reduce_kernel(
    const float* __restrict__ temp)
{
    const int idx = blockIdx.x * 256 + threadIdx.x;   // 0..32767
    float M = -CUDART_INF_F;
    #pragma unroll
    for (int c = 0; c < 32; c++)
        M = fmaxf(M, g_partM[c * 32768 + idx]);

    float E = 0.0f, Tg = 0.0f;
    #pragma unroll
    for (int c = 0; c < 32; c++) {
        const float dm = g_partM[c * 32768 + idx] - M;   // <= 0
        const float w  = ex2f(dm);
        const float Ec = g_partE[c * 32768 + idx];
        const float Tc = g_partT[c * 32768 + idx];
        E  = fmaf(w, Ec, E);
        Tg = fmaf(w, fmaf(dm, Ec, Tc), Tg);  // w*(Tc + dm*Ec)
    }
    const float invs = -(*temp) / LOG2E;     // 1/s
    // E >= 1 (the argmax chunk contributes its max term = 1).
    const float weighted = invs * (Tg / E + M);

    __shared__ float red[256];
    red[threadIdx.x] = weighted;
    __syncthreads();
    #pragma unroll
    for (int off = 128; off > 0; off >>= 1) {
        if (threadIdx.x < off) red[threadIdx.x] += red[threadIdx.x + off];
        __syncthreads();
    }
    if (threadIdx.x == 0)
        g_blocksum[blockIdx.x] = red[0];
}

// Final: sum 128 block partials, write the mean.
__global__ void fape_final_kernel(float* __restrict__ out) {
    const int tid = threadIdx.x;   // 128 threads
    float v = g_blocksum[tid];
    #pragma unroll
    for (int off = 16; off > 0; off >>= 1)
        v += __shfl_xor_sync(0xffffffffu, v, off);
    __shared__ float warp_s[4];
    if ((tid & 31) == 0) warp_s[tid >> 5] = v;
    __syncthreads();
    if (tid == 0)
        *out = (warp_s[0] + warp_s[1] + warp_s[2] + warp_s[3]) * (1.0f / (8.0f * 4096.0f));
}

extern "C" void kernel_launch(void* const* d_in, const int* in_sizes, int n_in,
                              void* d_out, int out_size) {
    const float* Xp   = (const float*)d_in[0];
    const float* Xt   = (const float*)d_in[1];
    const float* Rp   = (const float*)d_in[2];
    const float* tp   = (const float*)d_in[3];
    const float* Rt   = (const float*)d_in[4];
    const float* tt   = (const float*)d_in[5];
    const float* temp = (const float*)d_in[6];
    float* out = (float*)d_out;

    fape_fused_kernel<<<2048, 256>>>(Xp, Xt, Rp, tp, Rt, tt, temp);
    fape_reduce_kernel<<<128, 256>>>(temp);
    fape_final_kernel<<<1, 128>>>(out);
}

// round 12
// speedup vs baseline: 1.0241x; 1.0041x over previous
#include <cuda_runtime.h>
#include <cstdint>
#include <math_constants.h>

#define LOG2E 1.4426950408889634f

typedef unsigned long long u64;

// Scratch: 32 m-chunks x (8*4096) n's: locally-shifted partial sums + local max.
__device__ float g_partE[32 * 32768];
__device__ float g_partT[32 * 32768];
__device__ float g_partM[32 * 32768];
__device__ float g_blocksum[512];

__device__ __forceinline__ u64 f2fma(u64 a, u64 b, u64 c) {
    u64 r; asm("fma.rn.f32x2 %0,%1,%2,%3;" : "=l"(r) : "l"(a), "l"(b), "l"(c)); return r;
}
__device__ __forceinline__ u64 f2add(u64 a, u64 b) {
    u64 r; asm("add.rn.f32x2 %0,%1,%2;" : "=l"(r) : "l"(a), "l"(b)); return r;
}
__device__ __forceinline__ u64 f2mul(u64 a, u64 b) {
    u64 r; asm("mul.rn.f32x2 %0,%1,%2;" : "=l"(r) : "l"(a), "l"(b)); return r;
}
__device__ __forceinline__ u64 pk(float lo, float hi) {
    u64 r; asm("mov.b64 %0,{%1,%2};" : "=l"(r) : "f"(lo), "f"(hi)); return r;
}
__device__ __forceinline__ void up(u64 v, float& lo, float& hi) {
    asm("mov.b64 {%0,%1},%2;" : "=f"(lo), "=f"(hi) : "l"(v));
}
__device__ __forceinline__ float ex2f(float x) {
    float r; asm("ex2.approx.f32 %0,%1;" : "=f"(r) : "f"(x)); return r;
}

// B=8, N=4096, M=4096, D=3 hardcoded.
// Grid: 2048 blocks = 8 batches x 8 n-chunks x 32 m-chunks.
// Block: 256 threads; each thread owns 2 n's; block owns 128 m's.
// Online softmax, 16-m tiles. v loaded ONCE per k, feeding both n chains.
__global__ void __launch_bounds__(256, 3) fape_fused_kernel(
    const float* __restrict__ Xp,   // (8,4096,3)
    const float* __restrict__ Xt,   // (8,4096,3)
    const float* __restrict__ Rp,   // (8,3,3)
    const float* __restrict__ tp,   // (8,3)
    const float* __restrict__ Rt,   // (8,3,3)
    const float* __restrict__ tt,   // (8,3)
    const float* __restrict__ temp) // (1,)
{
    // 64 m-pair groups x 4 packed u64: [vx01, vy01, vz01, vw01].
    __shared__ __align__(16) u64 sm[64 * 4];   // 2 KB

    const int mchunk = blockIdx.x & 31;
    const int nchunk = (blockIdx.x >> 5) & 7;
    const int b      = blockIdx.x >> 8;
    const int tid    = threadIdx.x;

    const float T = *temp;
    const float s = -LOG2E / T;   // logit scale in log2 domain (s < 0)

    // ---- Fill smem: v = (s*-2*Xt', s*|Xt'|^2) for this block's 128 m's ----
    if (tid < 128) {
        const float* R  = Rt + b * 9;
        const float* tv = tt + b * 3;
        const float r00 = R[0], r01 = R[1], r02 = R[2];
        const float r10 = R[3], r11 = R[4], r12 = R[5];
        const float r20 = R[6], r21 = R[7], r22 = R[8];
        const float tx = tv[0], ty = tv[1], tz = tv[2];
        const float s2 = s * -2.0f;

        const float* xm = Xt + (size_t)(b * 4096 + mchunk * 128 + tid) * 3;
        const float x = xm[0], y = xm[1], z = xm[2];
        const float ax = r00 * x + r01 * y + r02 * z + tx;
        const float ay = r10 * x + r11 * y + r12 * z + ty;
        const float az = r20 * x + r21 * y + r22 * z + tz;
        const float sq = ax * ax + ay * ay + az * az;
        const int j = tid >> 1, h = tid & 1;
        float* w = (float*)(sm + j * 4);
        w[0 + h] = s2 * ax;   // vx
        w[2 + h] = s2 * ay;   // vy
        w[4 + h] = s2 * az;   // vz
        w[6 + h] = s * sq;    // vw
    }

    // ---- Per-thread: two n's ----
    const float* Rq = Rp + b * 9;
    const float* tq = tp + b * 3;
    const float q00 = Rq[0], q01 = Rq[1], q02 = Rq[2];
    const float q10 = Rq[3], q11 = Rq[4], q12 = Rq[5];
    const float q20 = Rq[6], q21 = Rq[7], q22 = Rq[8];
    const float u0 = tq[0], u1 = tq[1], u2 = tq[2];

    const int n0 = nchunk * 512 + tid;      // and n1 = n0 + 256
    const float* xa = Xp + (size_t)(b * 4096 + n0) * 3;
    const float* xb = xa + 256 * 3;

    const float ax0 = xa[0], ay0 = xa[1], az0 = xa[2];
    const float px0 = q00 * ax0 + q01 * ay0 + q02 * az0 + u0;
    const float py0 = q10 * ax0 + q11 * ay0 + q12 * az0 + u1;
    const float pz0 = q20 * ax0 + q21 * ay0 + q22 * az0 + u2;
    const float sc0 = s * (px0 * px0 + py0 * py0 + pz0 * pz0);

    const float ax1 = xb[0], ay1 = xb[1], az1 = xb[2];
    const float px1 = q00 * ax1 + q01 * ay1 + q02 * az1 + u0;
    const float py1 = q10 * ax1 + q11 * ay1 + q12 * az1 + u1;
    const float pz1 = q20 * ax1 + q21 * ay1 + q22 * az1 + u2;
    const float sc1 = s * (px1 * px1 + py1 * py1 + pz1 * pz1);

    const u64 Px0 = pk(px0, px0), Py0 = pk(py0, py0), Pz0 = pk(pz0, pz0);
    const u64 Px1 = pk(px1, px1), Py1 = pk(py1, py1), Pz1 = pk(pz1, pz1);

    // Online-softmax state per n: running max M, scaled sums Se = Σe, Sg = Σe*(g-M).
    float M0 = -1e30f, M1 = -1e30f;
    u64 Se0 = 0ull, Sg0 = 0ull, Se1 = 0ull, Sg1 = 0ull;

    __syncthreads();

    // 8 tiles x (8 groups = 16 m's); v loaded once per group for both n's.
    for (int t = 0; t < 8; t++) {
        const u64* base = sm + t * 32;

        u64 g0[8], g1[8];
        #pragma unroll
        for (int k = 0; k < 8; k++) {
            const ulonglong2 v1 = *(const ulonglong2*)(base + k * 4);     // vx, vy
            const ulonglong2 v2 = *(const ulonglong2*)(base + k * 4 + 2); // vz, vw
            u64 a = f2fma(Pz0, v2.x, v2.y);
            a = f2fma(Py0, v1.y, a);
            g0[k] = f2fma(Px0, v1.x, a);
            u64 c = f2fma(Pz1, v2.x, v2.y);
            c = f2fma(Py1, v1.y, c);
            g1[k] = f2fma(Px1, v1.x, c);
        }

        // ---- n0: tree max, rescale, exp-accumulate ----
        {
            float m8[8];
            #pragma unroll
            for (int k = 0; k < 8; k++) { float lo, hi; up(g0[k], lo, hi); m8[k] = fmaxf(lo, hi); }
            const float tm = fmaxf(fmaxf(fmaxf(m8[0], m8[1]), fmaxf(m8[2], m8[3])),
                                   fmaxf(fmaxf(m8[4], m8[5]), fmaxf(m8[6], m8[7])));
            const float Mn = fmaxf(M0, tm);
            const float ds = M0 - Mn;            // <= 0
            const float w  = ex2f(ds);
            const u64 D = pk(ds, ds), W = pk(w, w);
            Sg0 = f2mul(f2fma(D, Se0, Sg0), W);  // (Sg + dM*Se) * w
            Se0 = f2mul(Se0, W);
            M0 = Mn;
            const u64 NM = pk(-Mn, -Mn);
            #pragma unroll
            for (int k = 0; k < 8; k++) {
                const u64 dd = f2add(g0[k], NM); // shifted logit <= 0
                float a0, c0; up(dd, a0, c0);
                const u64 E = pk(ex2f(a0), ex2f(c0));
                Se0 = f2add(Se0, E);
                Sg0 = f2fma(E, dd, Sg0);
            }
        }
        // ---- n1 ----
        {
            float m8[8];
            #pragma unroll
            for (int k = 0; k < 8; k++) { float lo, hi; up(g1[k], lo, hi); m8[k] = fmaxf(lo, hi); }
            const float tm = fmaxf(fmaxf(fmaxf(m8[0], m8[1]), fmaxf(m8[2], m8[3])),
                                   fmaxf(fmaxf(m8[4], m8[5]), fmaxf(m8[6], m8[7])));
            const float Mn = fmaxf(M1, tm);
            const float ds = M1 - Mn;
            const float w  = ex2f(ds);
            const u64 D = pk(ds, ds), W = pk(w, w);
            Sg1 = f2mul(f2fma(D, Se1, Sg1), W);
            Se1 = f2mul(Se1, W);
            M1 = Mn;
            const u64 NM = pk(-Mn, -Mn);
            #pragma unroll
            for (int k = 0; k < 8; k++) {
                const u64 dd = f2add(g1[k], NM);
                float a0, c0; up(dd, a0, c0);
                const u64 E = pk(ex2f(a0), ex2f(c0));
                Se1 = f2add(Se1, E);
                Sg1 = f2fma(E, dd, Sg1);
            }
        }
    }

    // Write partials: (E_c, T_c, M_c) per (n, mchunk). Logit max M_c = sc + M.
    float e0, e1, t0, t1;
    const int gbase = mchunk * 32768 + b * 4096 + nchunk * 512 + tid;
    up(Se0, e0, e1); up(Sg0, t0, t1);
    g_partE[gbase] = e0 + e1;
    g_partT[gbase] = t0 + t1;
    g_partM[gbase] = sc0 + M0;
    up(Se1, e0, e1); up(Sg1, t0, t1);
    g_partE[gbase + 256] = e0 + e1;
    g_partT[gbase + 256] = t0 + t1;
    g_partM[gbase + 256] = sc1 + M1;
}

// Exact combine of locally-shifted partials: 4 threads per n (8 chunks each),
// shfl-combined; per-block partial sums. Grid 512 x 256.
__global__ void __launch_bounds__(256) fape_reduce_kernel(
    const float* __restrict__ temp)
{
    const int t    = blockIdx.x * 256 + threadIdx.x;   // 0..131071
    const int n    = t >> 2;                           // 0..32767
    const int part = t & 3;
    const int cb   = part * 8;

    float Mc[8];
    float M = -CUDART_INF_F;
    #pragma unroll
    for (int i = 0; i < 8; i++) {
        Mc[i] = g_partM[(cb + i) * 32768 + n];
        M = fmaxf(M, Mc[i]);
    }
    M = fmaxf(M, __shfl_xor_sync(0xffffffffu, M, 1));
    M = fmaxf(M, __shfl_xor_sync(0xffffffffu, M, 2));

    float E = 0.0f, Tg = 0.0f;
    #pragma unroll
    for (int i = 0; i < 8; i++) {
        const float dm = Mc[i] - M;                    // <= 0
        const float w  = ex2f(dm);
        const float Ec = g_partE[(cb + i) * 32768 + n];
        const float Tc = g_partT[(cb + i) * 32768 + n];
        E  = fmaf(w, Ec, E);
        Tg = fmaf(w, fmaf(dm, Ec, Tc), Tg);            // w*(Tc + dm*Ec)
    }
    E  += __shfl_xor_sync(0xffffffffu, E, 1);
    E  += __shfl_xor_sync(0xffffffffu, E, 2);
    Tg += __shfl_xor_sync(0xffffffffu, Tg, 1);
    Tg += __shfl_xor_sync(0xffffffffu, Tg, 2);

    const float invs = -(*temp) / LOG2E;               // 1/s
    // E >= 1 (the argmax chunk contributes its max term = 1).
    const float weighted = (part == 0) ? invs * (Tg / E + M) : 0.0f;

    __shared__ float red[256];
    red[threadIdx.x] = weighted;
    __syncthreads();
    #pragma unroll
    for (int off = 128; off > 0; off >>= 1) {
        if (threadIdx.x < off) red[threadIdx.x] += red[threadIdx.x + off];
        __syncthreads();
    }
    if (threadIdx.x == 0)
        g_blocksum[blockIdx.x] = red[0];
}

// Final: sum 512 block partials, write the mean.
__global__ void fape_final_kernel(float* __restrict__ out) {
    const int tid = threadIdx.x;   // 512 threads
    float v = g_blocksum[tid];
    #pragma unroll
    for (int off = 16; off > 0; off >>= 1)
        v += __shfl_xor_sync(0xffffffffu, v, off);
    __shared__ float ws[16];
    if ((tid & 31) == 0) ws[tid >> 5] = v;
    __syncthreads();
    if (tid < 16) {
        float x = ws[tid];
        #pragma unroll
        for (int off = 8; off > 0; off >>= 1)
            x += __shfl_xor_sync(0x0000ffffu, x, off);
        if (tid == 0)
            *out = x * (1.0f / (8.0f * 4096.0f));
    }
}

extern "C" void kernel_launch(void* const* d_in, const int* in_sizes, int n_in,
                              void* d_out, int out_size) {
    const float* Xp   = (const float*)d_in[0];
    const float* Xt   = (const float*)d_in[1];
    const float* Rp   = (const float*)d_in[2];
    const float* tp   = (const float*)d_in[3];
    const float* Rt   = (const float*)d_in[4];
    const float* tt   = (const float*)d_in[5];
    const float* temp = (const float*)d_in[6];
    float* out = (float*)d_out;

    fape_fused_kernel<<<2048, 256>>>(Xp, Xt, Rp, tp, Rt, tt, temp);
    fape_reduce_kernel<<<512, 256>>>(temp);
    fape_final_kernel<<<1, 512>>>(out);
}

// round 13
// speedup vs baseline: 1.0331x; 1.0088x over previous
#include <cuda_runtime.h>
#include <cstdint>
#include <math_constants.h>

#define LOG2E 1.4426950408889634f

typedef unsigned long long u64;

// Scratch: 32 m-chunks x (8*4096) n's: locally-shifted partial sums + local max.
__device__ float g_partE[32 * 32768];
__device__ float g_partT[32 * 32768];
__device__ float g_partM[32 * 32768];
__device__ float g_blocksum[512];

__device__ __forceinline__ u64 f2fma(u64 a, u64 b, u64 c) {
    u64 r; asm("fma.rn.f32x2 %0,%1,%2,%3;" : "=l"(r) : "l"(a), "l"(b), "l"(c)); return r;
}
__device__ __forceinline__ u64 f2add(u64 a, u64 b) {
    u64 r; asm("add.rn.f32x2 %0,%1,%2;" : "=l"(r) : "l"(a), "l"(b)); return r;
}
__device__ __forceinline__ u64 f2mul(u64 a, u64 b) {
    u64 r; asm("mul.rn.f32x2 %0,%1,%2;" : "=l"(r) : "l"(a), "l"(b)); return r;
}
__device__ __forceinline__ u64 pk(float lo, float hi) {
    u64 r; asm("mov.b64 %0,{%1,%2};" : "=l"(r) : "f"(lo), "f"(hi)); return r;
}
__device__ __forceinline__ void up(u64 v, float& lo, float& hi) {
    asm("mov.b64 {%0,%1},%2;" : "=f"(lo), "=f"(hi) : "l"(v));
}
__device__ __forceinline__ float ex2f(float x) {
    float r; asm("ex2.approx.f32 %0,%1;" : "=f"(r) : "f"(x)); return r;
}

// B=8, N=4096, M=4096, D=3 hardcoded.
// Grid: 1024 blocks = 8 batches x 4 n-chunks x 32 m-chunks.
// Block: 256 threads; each thread owns 4 n's (4 independent online-softmax
// chains for ILP); block owns 128 m's. 8-m tiles.
__global__ void __launch_bounds__(256, 2) fape_fused_kernel(
    const float* __restrict__ Xp,   // (8,4096,3)
    const float* __restrict__ Xt,   // (8,4096,3)
    const float* __restrict__ Rp,   // (8,3,3)
    const float* __restrict__ tp,   // (8,3)
    const float* __restrict__ Rt,   // (8,3,3)
    const float* __restrict__ tt,   // (8,3)
    const float* __restrict__ temp) // (1,)
{
    // 64 m-pair groups x 4 packed u64: [vx01, vy01, vz01, vw01].
    __shared__ __align__(16) u64 sm[64 * 4];   // 2 KB

    const int mchunk = blockIdx.x & 31;
    const int nchunk = (blockIdx.x >> 5) & 3;
    const int b      = blockIdx.x >> 7;
    const int tid    = threadIdx.x;

    const float T = *temp;
    const float s = -LOG2E / T;   // logit scale in log2 domain (s < 0)

    // ---- Fill smem: v = (s*-2*Xt', s*|Xt'|^2) for this block's 128 m's ----
    if (tid < 128) {
        const float* R  = Rt + b * 9;
        const float* tv = tt + b * 3;
        const float r00 = R[0], r01 = R[1], r02 = R[2];
        const float r10 = R[3], r11 = R[4], r12 = R[5];
        const float r20 = R[6], r21 = R[7], r22 = R[8];
        const float tx = tv[0], ty = tv[1], tz = tv[2];
        const float s2 = s * -2.0f;

        const float* xm = Xt + (size_t)(b * 4096 + mchunk * 128 + tid) * 3;
        const float x = xm[0], y = xm[1], z = xm[2];
        const float ax = r00 * x + r01 * y + r02 * z + tx;
        const float ay = r10 * x + r11 * y + r12 * z + ty;
        const float az = r20 * x + r21 * y + r22 * z + tz;
        const float sq = ax * ax + ay * ay + az * az;
        const int j = tid >> 1, h = tid & 1;
        float* w = (float*)(sm + j * 4);
        w[0 + h] = s2 * ax;   // vx
        w[2 + h] = s2 * ay;   // vy
        w[4 + h] = s2 * az;   // vz
        w[6 + h] = s * sq;    // vw
    }

    // ---- Per-thread: four n's ----
    const float* Rq = Rp + b * 9;
    const float* tq = tp + b * 3;
    const float q00 = Rq[0], q01 = Rq[1], q02 = Rq[2];
    const float q10 = Rq[3], q11 = Rq[4], q12 = Rq[5];
    const float q20 = Rq[6], q21 = Rq[7], q22 = Rq[8];
    const float u0 = tq[0], u1 = tq[1], u2 = tq[2];

    const int n0 = nchunk * 1024 + tid;   // n_i = n0 + i*256
    u64 PX[4], PY[4], PZ[4];
    float SC[4];
    #pragma unroll
    for (int i = 0; i < 4; i++) {
        const float* xa = Xp + (size_t)(b * 4096 + n0 + i * 256) * 3;
        const float ax = xa[0], ay = xa[1], az = xa[2];
        const float px = q00 * ax + q01 * ay + q02 * az + u0;
        const float py = q10 * ax + q11 * ay + q12 * az + u1;
        const float pz = q20 * ax + q21 * ay + q22 * az + u2;
        SC[i] = s * (px * px + py * py + pz * pz);
        PX[i] = pk(px, px);
        PY[i] = pk(py, py);
        PZ[i] = pk(pz, pz);
    }

    // Online-softmax state per n.
    float Mx[4] = { -1e30f, -1e30f, -1e30f, -1e30f };
    u64 SE[4] = { 0ull, 0ull, 0ull, 0ull };
    u64 SG[4] = { 0ull, 0ull, 0ull, 0ull };

    __syncthreads();

    // 16 tiles x (4 groups = 8 m's); v loaded once per group, feeds 4 chains.
    for (int t = 0; t < 16; t++) {
        const u64* base = sm + t * 16;

        u64 g[4][4];   // [chain][group]
        #pragma unroll
        for (int k = 0; k < 4; k++) {
            const ulonglong2 v1 = *(const ulonglong2*)(base + k * 4);     // vx, vy
            const ulonglong2 v2 = *(const ulonglong2*)(base + k * 4 + 2); // vz, vw
            #pragma unroll
            for (int i = 0; i < 4; i++) {
                u64 a = f2fma(PZ[i], v2.x, v2.y);
                a = f2fma(PY[i], v1.y, a);
                g[i][k] = f2fma(PX[i], v1.x, a);
            }
        }

        #pragma unroll
        for (int i = 0; i < 4; i++) {
            // Tile max (7 FMNMX, ALU pipe).
            float m4[4];
            #pragma unroll
            for (int k = 0; k < 4; k++) { float lo, hi; up(g[i][k], lo, hi); m4[k] = fmaxf(lo, hi); }
            const float tm = fmaxf(fmaxf(m4[0], m4[1]), fmaxf(m4[2], m4[3]));

            // Running max + branchless rescale (once per 8 m's).
            const float Mn = fmaxf(Mx[i], tm);
            const float ds = Mx[i] - Mn;         // <= 0
            const float w  = ex2f(ds);
            const u64 D = pk(ds, ds), W = pk(w, w);
            SG[i] = f2mul(f2fma(D, SE[i], SG[i]), W);  // (Sg + dM*Se) * w
            SE[i] = f2mul(SE[i], W);
            Mx[i] = Mn;

            const u64 NM = pk(-Mn, -Mn);
            u64 se = SE[i], sg = SG[i];
            #pragma unroll
            for (int k = 0; k < 4; k++) {
                const u64 dd = f2add(g[i][k], NM);   // shifted logit <= 0
                float a0, c0; up(dd, a0, c0);
                const u64 E = pk(ex2f(a0), ex2f(c0));
                se = f2add(se, E);
                sg = f2fma(E, dd, sg);
            }
            SE[i] = se;
            SG[i] = sg;
        }
    }

    // Write partials: (E_c, T_c, M_c) per (n, mchunk). Logit max M_c = sc + M.
    #pragma unroll
    for (int i = 0; i < 4; i++) {
        float e0, e1, t0, t1;
        up(SE[i], e0, e1);
        up(SG[i], t0, t1);
        const int gi = mchunk * 32768 + b * 4096 + n0 + i * 256;
        g_partE[gi] = e0 + e1;
        g_partT[gi] = t0 + t1;
        g_partM[gi] = SC[i] + Mx[i];
    }
}

// Exact combine of locally-shifted partials: 4 threads per n (8 chunks each),
// shfl-combined; per-block partial sums. Grid 512 x 256.
__global__ void __launch_bounds__(256) fape_reduce_kernel(
    const float* __restrict__ temp)
{
    const int t    = blockIdx.x * 256 + threadIdx.x;   // 0..131071
    const int n    = t >> 2;                           // 0..32767
    const int part = t & 3;
    const int cb   = part * 8;

    float Mc[8];
    float M = -CUDART_INF_F;
    #pragma unroll
    for (int i = 0; i < 8; i++) {
        Mc[i] = g_partM[(cb + i) * 32768 + n];
        M = fmaxf(M, Mc[i]);
    }
    M = fmaxf(M, __shfl_xor_sync(0xffffffffu, M, 1));
    M = fmaxf(M, __shfl_xor_sync(0xffffffffu, M, 2));

    float E = 0.0f, Tg = 0.0f;
    #pragma unroll
    for (int i = 0; i < 8; i++) {
        const float dm = Mc[i] - M;                    // <= 0
        const float w  = ex2f(dm);
        const float Ec = g_partE[(cb + i) * 32768 + n];
        const float Tc = g_partT[(cb + i) * 32768 + n];
        E  = fmaf(w, Ec, E);
        Tg = fmaf(w, fmaf(dm, Ec, Tc), Tg);            // w*(Tc + dm*Ec)
    }
    E  += __shfl_xor_sync(0xffffffffu, E, 1);
    E  += __shfl_xor_sync(0xffffffffu, E, 2);
    Tg += __shfl_xor_sync(0xffffffffu, Tg, 1);
    Tg += __shfl_xor_sync(0xffffffffu, Tg, 2);

    const float invs = -(*temp) / LOG2E;               // 1/s
    // E >= 1 (the argmax chunk contributes its max term = 1).
    const float weighted = (part == 0) ? invs * (Tg / E + M) : 0.0f;

    __shared__ float red[256];
    red[threadIdx.x] = weighted;
    __syncthreads();
    #pragma unroll
    for (int off = 128; off > 0; off >>= 1) {
        if (threadIdx.x < off) red[threadIdx.x] += red[threadIdx.x + off];
        __syncthreads();
    }
    if (threadIdx.x == 0)
        g_blocksum[blockIdx.x] = red[0];
}

// Final: sum 512 block partials, write the mean.
__global__ void fape_final_kernel(float* __restrict__ out) {
    const int tid = threadIdx.x;   // 512 threads
    float v = g_blocksum[tid];
    #pragma unroll
    for (int off = 16; off > 0; off >>= 1)
        v += __shfl_xor_sync(0xffffffffu, v, off);
    __shared__ float ws[16];
    if ((tid & 31) == 0) ws[tid >> 5] = v;
    __syncthreads();
    if (tid < 16) {
        float x = ws[tid];
        #pragma unroll
        for (int off = 8; off > 0; off >>= 1)
            x += __shfl_xor_sync(0x0000ffffu, x, off);
        if (tid == 0)
            *out = x * (1.0f / (8.0f * 4096.0f));
    }
}

extern "C" void kernel_launch(void* const* d_in, const int* in_sizes, int n_in,
                              void* d_out, int out_size) {
    const float* Xp   = (const float*)d_in[0];
    const float* Xt   = (const float*)d_in[1];
    const float* Rp   = (const float*)d_in[2];
    const float* tp   = (const float*)d_in[3];
    const float* Rt   = (const float*)d_in[4];
    const float* tt   = (const float*)d_in[5];
    const float* temp = (const float*)d_in[6];
    float* out = (float*)d_out;

    fape_fused_kernel<<<1024, 256>>>(Xp, Xt, Rp, tp, Rt, tt, temp);
    fape_reduce_kernel<<<512, 256>>>(temp);
    fape_final_kernel<<<1, 512>>>(out);
}

// round 14
// speedup vs baseline: 1.0684x; 1.0342x over previous
#include <cuda_runtime.h>
#include <cstdint>
#include <math_constants.h>

#define LOG2E 1.4426950408889634f

typedef unsigned long long u64;

// Scratch: 32 m-chunks x (8*4096) n's: locally-shifted partial sums + local max.
__device__ float g_partE[32 * 32768];
__device__ float g_partT[32 * 32768];
__device__ float g_partM[32 * 32768];

__device__ __forceinline__ u64 f2fma(u64 a, u64 b, u64 c) {
    u64 r; asm("fma.rn.f32x2 %0,%1,%2,%3;" : "=l"(r) : "l"(a), "l"(b), "l"(c)); return r;
}
__device__ __forceinline__ u64 f2add(u64 a, u64 b) {
    u64 r; asm("add.rn.f32x2 %0,%1,%2;" : "=l"(r) : "l"(a), "l"(b)); return r;
}
__device__ __forceinline__ u64 f2mul(u64 a, u64 b) {
    u64 r; asm("mul.rn.f32x2 %0,%1,%2;" : "=l"(r) : "l"(a), "l"(b)); return r;
}
__device__ __forceinline__ u64 pk(float lo, float hi) {
    u64 r; asm("mov.b64 %0,{%1,%2};" : "=l"(r) : "f"(lo), "f"(hi)); return r;
}
__device__ __forceinline__ void up(u64 v, float& lo, float& hi) {
    asm("mov.b64 {%0,%1},%2;" : "=f"(lo), "=f"(hi) : "l"(v));
}
__device__ __forceinline__ float ex2f(float x) {
    float r; asm("ex2.approx.f32 %0,%1;" : "=f"(r) : "f"(x)); return r;
}

// B=8, N=4096, M=4096, D=3 hardcoded.
// Grid: 1024 blocks = 8 batches x 4 n-chunks x 32 m-chunks.
// Block: 256 threads; each thread owns 4 n's; block owns 128 m's. 8-m tiles.
// Lagged-shift online softmax: accumulate 2^(g-S) with shift S updated only
// on a rare warp-uniform vote (when a tile max exceeds S+60). True max M
// tracked cheaply; partials rescaled S->M at writeback.
__global__ void __launch_bounds__(256, 2) fape_fused_kernel(
    const float* __restrict__ Xp,   // (8,4096,3)
    const float* __restrict__ Xt,   // (8,4096,3)
    const float* __restrict__ Rp,   // (8,3,3)
    const float* __restrict__ tp,   // (8,3)
    const float* __restrict__ Rt,   // (8,3,3)
    const float* __restrict__ tt,   // (8,3)
    const float* __restrict__ temp, // (1,)
    float* __restrict__ out)
{
    // 64 m-pair groups x 4 packed u64: [vx01, vy01, vz01, vw01].
    __shared__ __align__(16) u64 sm[64 * 4];   // 2 KB

    const int mchunk = blockIdx.x & 31;
    const int nchunk = (blockIdx.x >> 5) & 3;
    const int b      = blockIdx.x >> 7;
    const int tid    = threadIdx.x;

    if (blockIdx.x == 0 && tid == 0) *out = 0.0f;   // reduce kernel accumulates

    const float T = *temp;
    const float s = -LOG2E / T;   // logit scale in log2 domain (s < 0)

    // ---- Fill smem: v = (s*-2*Xt', s*|Xt'|^2) for this block's 128 m's ----
    if (tid < 128) {
        const float* R  = Rt + b * 9;
        const float* tv = tt + b * 3;
        const float r00 = R[0], r01 = R[1], r02 = R[2];
        const float r10 = R[3], r11 = R[4], r12 = R[5];
        const float r20 = R[6], r21 = R[7], r22 = R[8];
        const float tx = tv[0], ty = tv[1], tz = tv[2];
        const float s2 = s * -2.0f;

        const float* xm = Xt + (size_t)(b * 4096 + mchunk * 128 + tid) * 3;
        const float x = xm[0], y = xm[1], z = xm[2];
        const float ax = r00 * x + r01 * y + r02 * z + tx;
        const float ay = r10 * x + r11 * y + r12 * z + ty;
        const float az = r20 * x + r21 * y + r22 * z + tz;
        const float sq = ax * ax + ay * ay + az * az;
        const int j = tid >> 1, h = tid & 1;
        float* w = (float*)(sm + j * 4);
        w[0 + h] = s2 * ax;   // vx
        w[2 + h] = s2 * ay;   // vy
        w[4 + h] = s2 * az;   // vz
        w[6 + h] = s * sq;    // vw
    }

    // ---- Per-thread: four n's ----
    const float* Rq = Rp + b * 9;
    const float* tq = tp + b * 3;
    const float q00 = Rq[0], q01 = Rq[1], q02 = Rq[2];
    const float q10 = Rq[3], q11 = Rq[4], q12 = Rq[5];
    const float q20 = Rq[6], q21 = Rq[7], q22 = Rq[8];
    const float u0 = tq[0], u1 = tq[1], u2 = tq[2];

    const int n0 = nchunk * 1024 + tid;   // n_i = n0 + i*256
    u64 PX[4], PY[4], PZ[4];
    float SC[4];
    #pragma unroll
    for (int i = 0; i < 4; i++) {
        const float* xa = Xp + (size_t)(b * 4096 + n0 + i * 256) * 3;
        const float ax = xa[0], ay = xa[1], az = xa[2];
        const float px = q00 * ax + q01 * ay + q02 * az + u0;
        const float py = q10 * ax + q11 * ay + q12 * az + u1;
        const float pz = q20 * ax + q21 * ay + q22 * az + u2;
        SC[i] = s * (px * px + py * py + pz * pz);
        PX[i] = pk(px, px);
        PY[i] = pk(py, py);
        PZ[i] = pk(pz, pz);
    }

    // Per-chain state: true max Mx, shift Sh (constant between rescales).
    float Mx[4] = { -1e30f, -1e30f, -1e30f, -1e30f };
    float Sh[4] = { -1e30f, -1e30f, -1e30f, -1e30f };
    u64 SE[4] = { 0ull, 0ull, 0ull, 0ull };
    u64 SG[4] = { 0ull, 0ull, 0ull, 0ull };

    __syncthreads();

    // 16 tiles x (4 groups = 8 m's); v loaded once per group, feeds 4 chains.
    for (int t = 0; t < 16; t++) {
        const u64* base = sm + t * 16;

        u64 g[4][4];   // [chain][group]
        #pragma unroll
        for (int k = 0; k < 4; k++) {
            const ulonglong2 v1 = *(const ulonglong2*)(base + k * 4);     // vx, vy
            const ulonglong2 v2 = *(const ulonglong2*)(base + k * 4 + 2); // vz, vw
            #pragma unroll
            for (int i = 0; i < 4; i++) {
                u64 a = f2fma(PZ[i], v2.x, v2.y);
                a = f2fma(PY[i], v1.y, a);
                g[i][k] = f2fma(PX[i], v1.x, a);
            }
        }

        // Tile maxes (ALU pipe, off the accumulate critical path).
        bool need = false;
        #pragma unroll
        for (int i = 0; i < 4; i++) {
            float m4[4];
            #pragma unroll
            for (int k = 0; k < 4; k++) { float lo, hi; up(g[i][k], lo, hi); m4[k] = fmaxf(lo, hi); }
            const float tm = fmaxf(fmaxf(m4[0], m4[1]), fmaxf(m4[2], m4[3]));
            Mx[i] = fmaxf(Mx[i], tm);
            need |= (tm > Sh[i] + 60.0f);
        }

        // Rare warp-uniform rescale: bring shift up to the true max.
        if (__any_sync(0xffffffffu, need)) {
            #pragma unroll
            for (int i = 0; i < 4; i++) {
                const float ds = Sh[i] - Mx[i];      // <= 0, finite
                const float w  = ex2f(ds);
                const u64 D = pk(ds, ds), W = pk(w, w);
                SG[i] = f2mul(f2fma(D, SE[i], SG[i]), W);   // (Sg + ds*Se) * w
                SE[i] = f2mul(SE[i], W);
                Sh[i] = Mx[i];
            }
        }

        // Exp-accumulate against the (lagged) shift. Terms may exceed 1;
        // bounded by 2^60 so fp32 cannot overflow.
        #pragma unroll
        for (int i = 0; i < 4; i++) {
            const u64 NS = pk(-Sh[i], -Sh[i]);
            u64 se = SE[i], sg = SG[i];
            #pragma unroll
            for (int k = 0; k < 4; k++) {
                const u64 dd = f2add(g[i][k], NS);
                float a0, c0; up(dd, a0, c0);
                const u64 E = pk(ex2f(a0), ex2f(c0));
                se = f2add(se, E);
                sg = f2fma(E, dd, sg);
            }
            SE[i] = se;
            SG[i] = sg;
        }
    }

    // Writeback: rescale Sh -> Mx so partials are (E, T, M) as before.
    #pragma unroll
    for (int i = 0; i < 4; i++) {
        float e0, e1, t0, t1;
        up(SE[i], e0, e1);
        up(SG[i], t0, t1);
        const float eS = e0 + e1;
        const float tS = t0 + t1;
        const float ds = Sh[i] - Mx[i];              // <= 0
        const float w  = ex2f(ds);
        const int gi = mchunk * 32768 + b * 4096 + n0 + i * 256;
        g_partE[gi] = eS * w;
        g_partT[gi] = (tS + ds * eS) * w;
        g_partM[gi] = SC[i] + Mx[i];
    }
}

// Exact combine of locally-shifted partials: 4 threads per n (8 chunks each),
// shfl-combined; block sums accumulated straight into out. Grid 512 x 256.
__global__ void __launch_bounds__(256) fape_reduce_kernel(
    const float* __restrict__ temp, float* __restrict__ out)
{
    const int t    = blockIdx.x * 256 + threadIdx.x;   // 0..131071
    const int n    = t >> 2;                           // 0..32767
    const int part = t & 3;
    const int cb   = part * 8;

    float Mc[8];
    float M = -CUDART_INF_F;
    #pragma unroll
    for (int i = 0; i < 8; i++) {
        Mc[i] = g_partM[(cb + i) * 32768 + n];
        M = fmaxf(M, Mc[i]);
    }
    M = fmaxf(M, __shfl_xor_sync(0xffffffffu, M, 1));
    M = fmaxf(M, __shfl_xor_sync(0xffffffffu, M, 2));

    float E = 0.0f, Tg = 0.0f;
    #pragma unroll
    for (int i = 0; i < 8; i++) {
        const float dm = Mc[i] - M;                    // <= 0
        const float w  = ex2f(dm);
        const float Ec = g_partE[(cb + i) * 32768 + n];
        const float Tc = g_partT[(cb + i) * 32768 + n];
        E  = fmaf(w, Ec, E);
        Tg = fmaf(w, fmaf(dm, Ec, Tc), Tg);            // w*(Tc + dm*Ec)
    }
    E  += __shfl_xor_sync(0xffffffffu, E, 1);
    E  += __shfl_xor_sync(0xffffffffu, E, 2);
    Tg += __shfl_xor_sync(0xffffffffu, Tg, 1);
    Tg += __shfl_xor_sync(0xffffffffu, Tg, 2);

    const float invs = -(*temp) / LOG2E;               // 1/s
    // E >= 1 (the argmax chunk contributes its max term = 1).
    const float weighted = (part == 0)
        ? invs * (Tg / E + M) * (1.0f / (8.0f * 4096.0f)) : 0.0f;

    __shared__ float red[256];
    red[threadIdx.x] = weighted;
    __syncthreads();
    #pragma unroll
    for (int off = 128; off > 0; off >>= 1) {
        if (threadIdx.x < off) red[threadIdx.x] += red[threadIdx.x + off];
        __syncthreads();
    }
    if (threadIdx.x == 0)
        atomicAdd(out, red[0]);
}

extern "C" void kernel_launch(void* const* d_in, const int* in_sizes, int n_in,
                              void* d_out, int out_size) {
    const float* Xp   = (const float*)d_in[0];
    const float* Xt   = (const float*)d_in[1];
    const float* Rp   = (const float*)d_in[2];
    const float* tp   = (const float*)d_in[3];
    const float* Rt   = (const float*)d_in[4];
    const float* tt   = (const float*)d_in[5];
    const float* temp = (const float*)d_in[6];
    float* out = (float*)d_out;

    fape_fused_kernel<<<1024, 256>>>(Xp, Xt, Rp, tp, Rt, tt, temp, out);
    fape_reduce_kernel<<<512, 256>>>(temp, out);
}